// round 10
// baseline (speedup 1.0000x reference)
#include <cuda_runtime.h>
#include <cstdint>

// Problem constants
#define NBATCH 64
#define NBINS  256
#define ELEMS_PER_BATCH (256*32*32)          // 262144 floats per batch per tensor
#define F4_PER_BATCH    (ELEMS_PER_BATCH/4)  // 65536 float4
#define CHUNKS 4                             // blocks per (batch, tensor)
#define F4_PER_CHUNK (F4_PER_BATCH/CHUNKS)   // 16384 float4 per block
#define HIST_THREADS 512
#define BLOCKS_PER_BATCH (2*CHUNKS)          // 8 (both tensors)
#define NSTAGES (F4_PER_CHUNK/HIST_THREADS)  // 32 stages of 512 f4 per block
#define HCOLS 16                             // histogram lane-columns (tid & 15)

// Scratch (no device allocation allowed).
__device__ unsigned int g_part[2][NBATCH][CHUNKS][NBINS];
__device__ float        g_kl[NBATCH];
__device__ unsigned int g_bctr[NBATCH];      // per-batch tickets (reset by winner)
__device__ unsigned int g_ctr;               // global ticket (reset by final block)

// cp.async helpers
__device__ __forceinline__ void cp_async16(uint32_t smem_dst, const void* gsrc) {
    asm volatile("cp.async.cg.shared.global [%0], [%1], 16;"
                 :: "r"(smem_dst), "l"(gsrc));
}
__device__ __forceinline__ void cp_commit() {
    asm volatile("cp.async.commit_group;");
}
template <int N>
__device__ __forceinline__ void cp_wait() {
    asm volatile("cp.async.wait_group %0;" :: "n"(N));
}

// ---------------------------------------------------------------------------
// Single fused kernel. grid = (CHUNKS, NBATCH, 2) = 512 blocks, block = 512.
// Static smem ~34.5 KB (16 KB hist + 16 KB staging) -> fits default limit,
// 4 blocks/SM = 64 warps (full occupancy).
// Feed: per-thread cp.async double buffer — loads occupy no registers and
// never block the warp; one 16B line per thread permanently in flight.
// Hist: sh[bin][tid&15] — at most 2-way same-column collisions.
// ---------------------------------------------------------------------------
__global__ void __launch_bounds__(HIST_THREADS, 4) fused_kernel(
    const float4* __restrict__ feat_s, const float4* __restrict__ feat_t,
    float* __restrict__ out) {

    __shared__ unsigned int sh[NBINS][HCOLS];    // 16 KB
    __shared__ float4 stage[2][HIST_THREADS];    // 16 KB staging

    #pragma unroll
    for (int i = threadIdx.x; i < NBINS * HCOLS; i += HIST_THREADS)
        (&sh[0][0])[i] = 0u;
    __syncthreads();

    const float4* __restrict__ src = (blockIdx.z == 0) ? feat_s : feat_t;
    const int batch = blockIdx.y;
    const size_t base = (size_t)batch * F4_PER_BATCH
                      + (size_t)blockIdx.x * F4_PER_CHUNK;
    const int col = threadIdx.x & (HCOLS - 1);
    const float4* g = src + base + threadIdx.x;   // stride HIST_THREADS per stage

    float4* slot0 = &stage[0][threadIdx.x];
    float4* slot1 = &stage[1][threadIdx.x];
    uint32_t a0 = (uint32_t)__cvta_generic_to_shared(slot0);
    uint32_t a1 = (uint32_t)__cvta_generic_to_shared(slot1);

    // prologue: stage 0 in flight
    cp_async16(a0, g);
    cp_commit();

    #pragma unroll 1
    for (int s = 0; s < NSTAGES; s++) {
        if (s + 1 < NSTAGES) {
            // issue next stage into the other slot, then wait for current
            cp_async16((s & 1) ? a0 : a1, g + (size_t)(s + 1) * HIST_THREADS);
            cp_commit();
            cp_wait<1>();   // <=1 group outstanding -> stage s has landed
        } else {
            cp_wait<0>();
        }
        float4 v = (s & 1) ? *slot1 : *slot0;   // per-thread slot: no block sync
        atomicAdd(&sh[(int)v.x][col], 1u);
        atomicAdd(&sh[(int)v.y][col], 1u);
        atomicAdd(&sh[(int)v.z][col], 1u);
        atomicAdd(&sh[(int)v.w][col], 1u);
    }
    __syncthreads();

    // reduce HCOLS lane-columns per bin; rotated reads stay conflict-free
    if (threadIdx.x < NBINS) {
        const int b = threadIdx.x;
        unsigned int sum = 0;
        #pragma unroll
        for (int i = 0; i < HCOLS; i++) sum += sh[b][(i + b) & (HCOLS - 1)];
        g_part[blockIdx.z][batch][blockIdx.x][b] = sum;
    }
    __syncthreads();

    // ---- per-batch ticket ----
    __shared__ unsigned int s_bticket;
    if (threadIdx.x == 0) {
        __threadfence();
        s_bticket = atomicAdd(&g_bctr[batch], 1u);
    }
    __syncthreads();
    if (s_bticket != BLOCKS_PER_BATCH - 1) return;

    // ======== this block is last for its batch: compute KL(batch) ========
    __threadfence();  // acquire: make all partials of this batch visible

    const int b = threadIdx.x;            // bin id for threads < NBINS
    __shared__ float rs[NBINS];
    __shared__ float rt[NBINS];

    float es = 0.f, et = 0.f, as_ = 0.f, at_ = 0.f;
    if (b < NBINS) {
        unsigned int cs = 0, ct = 0;
        #pragma unroll
        for (int c = 0; c < CHUNKS; c++) {
            cs += *((volatile unsigned int*)&g_part[0][batch][c][b]);
            ct += *((volatile unsigned int*)&g_part[1][batch][c][b]);
        }
        as_ = (float)cs + 1e-8f;
        at_ = (float)ct + 1e-8f;
        es = sqrtf(sqrtf(as_));           // (a)^(1/T), T = 4
        et = sqrtf(sqrtf(at_));
        rs[b] = es; rt[b] = et;
    }
    __syncthreads();
    #pragma unroll
    for (int s = NBINS / 2; s > 0; s >>= 1) {
        if (b < s) { rs[b] += rs[b + s]; rt[b] += rt[b + s]; }
        __syncthreads();
    }
    float Ss = rs[0];
    float St = rt[0];
    __syncthreads();

    if (b < NBINS) {
        float pt = et / St;                                   // softmax target
        float diff = 0.25f * logf(at_ / as_) - logf(St / Ss); // log p_t - log p_s
        rs[b] = pt * diff;
    }
    __syncthreads();
    #pragma unroll
    for (int s = NBINS / 2; s > 0; s >>= 1) {
        if (b < s) rs[b] += rs[b + s];
        __syncthreads();
    }

    // publish per-batch KL, reset batch ticket, take global ticket
    __shared__ unsigned int s_ticket;
    if (threadIdx.x == 0) {
        g_kl[batch] = rs[0];
        g_bctr[batch] = 0;                 // ready for next graph replay
        __threadfence();
        s_ticket = atomicAdd(&g_ctr, 1u);
    }
    __syncthreads();
    if (s_ticket != NBATCH - 1) return;

    // ======== very last batch-winner: deterministic final sum ========
    __threadfence();
    __shared__ float red[NBATCH];
    if (threadIdx.x < NBATCH) red[threadIdx.x] = *((volatile float*)&g_kl[threadIdx.x]);
    __syncthreads();
    #pragma unroll
    for (int s = NBATCH / 2; s > 0; s >>= 1) {
        if (threadIdx.x < s) red[threadIdx.x] += red[threadIdx.x + s];
        __syncthreads();
    }
    if (threadIdx.x == 0) {
        out[0] = red[0] * (16.0f / (float)NBATCH);  // * T^2 / N
        g_ctr = 0;                                  // ready for next replay
    }
}

// ---------------------------------------------------------------------------
extern "C" void kernel_launch(void* const* d_in, const int* in_sizes, int n_in,
                              void* d_out, int out_size) {
    const float4* feat_s = (const float4*)d_in[0];
    const float4* feat_t = (const float4*)d_in[1];
    float* out = (float*)d_out;

    (void)in_sizes; (void)n_in; (void)out_size;

    dim3 grid(CHUNKS, NBATCH, 2);
    fused_kernel<<<grid, HIST_THREADS>>>(feat_s, feat_t, out);
}

// round 11
// speedup vs baseline: 1.0009x; 1.0009x over previous
#include <cuda_runtime.h>
#include <cstdint>

// Problem constants
#define NBATCH 64
#define NBINS  256
#define ELEMS_PER_BATCH (256*32*32)          // 262144 floats per batch per tensor
#define F4_PER_BATCH    (ELEMS_PER_BATCH/4)  // 65536 float4
#define CHUNKS 4                             // blocks per (batch, tensor)
#define F4_PER_CHUNK (F4_PER_BATCH/CHUNKS)   // 16384 float4 per block
#define HIST_THREADS 512
#define BLOCKS_PER_BATCH (2*CHUNKS)          // 8 (both tensors)
#define NSTAGES (F4_PER_CHUNK/HIST_THREADS)  // 32 stages of 512 f4 per block
#define HCOLS 16                             // histogram lane-columns (tid & 15)

// Scratch (no device allocation allowed).
__device__ unsigned int g_part[2][NBATCH][CHUNKS][NBINS];
__device__ float        g_kl[NBATCH];
__device__ unsigned int g_bctr[NBATCH];      // per-batch tickets (reset by winner)
__device__ unsigned int g_ctr;               // global ticket (reset by final block)

// cp.async helpers
__device__ __forceinline__ void cp_async16(uint32_t smem_dst, const void* gsrc) {
    asm volatile("cp.async.cg.shared.global [%0], [%1], 16;"
                 :: "r"(smem_dst), "l"(gsrc));
}
__device__ __forceinline__ void cp_commit() {
    asm volatile("cp.async.commit_group;");
}
template <int N>
__device__ __forceinline__ void cp_wait() {
    asm volatile("cp.async.wait_group %0;" :: "n"(N));
}

// ---------------------------------------------------------------------------
// Single fused kernel. grid = (CHUNKS, NBATCH, 2) = 512 blocks, block = 512.
// Static smem ~34.5 KB (16 KB hist + 16 KB staging) -> fits default limit,
// 4 blocks/SM = 64 warps (full occupancy).
// Feed: per-thread cp.async double buffer — loads occupy no registers and
// never block the warp; one 16B line per thread permanently in flight.
// Hist: sh[bin][tid&15] — at most 2-way same-column collisions.
// ---------------------------------------------------------------------------
__global__ void __launch_bounds__(HIST_THREADS, 4) fused_kernel(
    const float4* __restrict__ feat_s, const float4* __restrict__ feat_t,
    float* __restrict__ out) {

    __shared__ unsigned int sh[NBINS][HCOLS];    // 16 KB
    __shared__ float4 stage[2][HIST_THREADS];    // 16 KB staging

    #pragma unroll
    for (int i = threadIdx.x; i < NBINS * HCOLS; i += HIST_THREADS)
        (&sh[0][0])[i] = 0u;
    __syncthreads();

    const float4* __restrict__ src = (blockIdx.z == 0) ? feat_s : feat_t;
    const int batch = blockIdx.y;
    const size_t base = (size_t)batch * F4_PER_BATCH
                      + (size_t)blockIdx.x * F4_PER_CHUNK;
    const int col = threadIdx.x & (HCOLS - 1);
    const float4* g = src + base + threadIdx.x;   // stride HIST_THREADS per stage

    float4* slot0 = &stage[0][threadIdx.x];
    float4* slot1 = &stage[1][threadIdx.x];
    uint32_t a0 = (uint32_t)__cvta_generic_to_shared(slot0);
    uint32_t a1 = (uint32_t)__cvta_generic_to_shared(slot1);

    // prologue: stage 0 in flight
    cp_async16(a0, g);
    cp_commit();

    #pragma unroll 1
    for (int s = 0; s < NSTAGES; s++) {
        if (s + 1 < NSTAGES) {
            // issue next stage into the other slot, then wait for current
            cp_async16((s & 1) ? a0 : a1, g + (size_t)(s + 1) * HIST_THREADS);
            cp_commit();
            cp_wait<1>();   // <=1 group outstanding -> stage s has landed
        } else {
            cp_wait<0>();
        }
        float4 v = (s & 1) ? *slot1 : *slot0;   // per-thread slot: no block sync
        atomicAdd(&sh[(int)v.x][col], 1u);
        atomicAdd(&sh[(int)v.y][col], 1u);
        atomicAdd(&sh[(int)v.z][col], 1u);
        atomicAdd(&sh[(int)v.w][col], 1u);
    }
    __syncthreads();

    // reduce HCOLS lane-columns per bin; rotated reads stay conflict-free
    if (threadIdx.x < NBINS) {
        const int b = threadIdx.x;
        unsigned int sum = 0;
        #pragma unroll
        for (int i = 0; i < HCOLS; i++) sum += sh[b][(i + b) & (HCOLS - 1)];
        g_part[blockIdx.z][batch][blockIdx.x][b] = sum;
    }
    __syncthreads();

    // ---- per-batch ticket ----
    __shared__ unsigned int s_bticket;
    if (threadIdx.x == 0) {
        __threadfence();
        s_bticket = atomicAdd(&g_bctr[batch], 1u);
    }
    __syncthreads();
    if (s_bticket != BLOCKS_PER_BATCH - 1) return;

    // ======== this block is last for its batch: compute KL(batch) ========
    __threadfence();  // acquire: make all partials of this batch visible

    const int b = threadIdx.x;            // bin id for threads < NBINS
    __shared__ float rs[NBINS];
    __shared__ float rt[NBINS];

    float es = 0.f, et = 0.f, as_ = 0.f, at_ = 0.f;
    if (b < NBINS) {
        unsigned int cs = 0, ct = 0;
        #pragma unroll
        for (int c = 0; c < CHUNKS; c++) {
            cs += *((volatile unsigned int*)&g_part[0][batch][c][b]);
            ct += *((volatile unsigned int*)&g_part[1][batch][c][b]);
        }
        as_ = (float)cs + 1e-8f;
        at_ = (float)ct + 1e-8f;
        es = sqrtf(sqrtf(as_));           // (a)^(1/T), T = 4
        et = sqrtf(sqrtf(at_));
        rs[b] = es; rt[b] = et;
    }
    __syncthreads();
    #pragma unroll
    for (int s = NBINS / 2; s > 0; s >>= 1) {
        if (b < s) { rs[b] += rs[b + s]; rt[b] += rt[b + s]; }
        __syncthreads();
    }
    float Ss = rs[0];
    float St = rt[0];
    __syncthreads();

    if (b < NBINS) {
        float pt = et / St;                                   // softmax target
        float diff = 0.25f * logf(at_ / as_) - logf(St / Ss); // log p_t - log p_s
        rs[b] = pt * diff;
    }
    __syncthreads();
    #pragma unroll
    for (int s = NBINS / 2; s > 0; s >>= 1) {
        if (b < s) rs[b] += rs[b + s];
        __syncthreads();
    }

    // publish per-batch KL, reset batch ticket, take global ticket
    __shared__ unsigned int s_ticket;
    if (threadIdx.x == 0) {
        g_kl[batch] = rs[0];
        g_bctr[batch] = 0;                 // ready for next graph replay
        __threadfence();
        s_ticket = atomicAdd(&g_ctr, 1u);
    }
    __syncthreads();
    if (s_ticket != NBATCH - 1) return;

    // ======== very last batch-winner: deterministic final sum ========
    __threadfence();
    __shared__ float red[NBATCH];
    if (threadIdx.x < NBATCH) red[threadIdx.x] = *((volatile float*)&g_kl[threadIdx.x]);
    __syncthreads();
    #pragma unroll
    for (int s = NBATCH / 2; s > 0; s >>= 1) {
        if (threadIdx.x < s) red[threadIdx.x] += red[threadIdx.x + s];
        __syncthreads();
    }
    if (threadIdx.x == 0) {
        out[0] = red[0] * (16.0f / (float)NBATCH);  // * T^2 / N
        g_ctr = 0;                                  // ready for next replay
    }
}

// ---------------------------------------------------------------------------
extern "C" void kernel_launch(void* const* d_in, const int* in_sizes, int n_in,
                              void* d_out, int out_size) {
    const float4* feat_s = (const float4*)d_in[0];
    const float4* feat_t = (const float4*)d_in[1];
    float* out = (float*)d_out;

    (void)in_sizes; (void)n_in; (void)out_size;

    dim3 grid(CHUNKS, NBATCH, 2);
    fused_kernel<<<grid, HIST_THREADS>>>(feat_s, feat_t, out);
}